// round 15
// baseline (speedup 1.0000x reference)
#include <cuda_runtime.h>
#include <cuda_bf16.h>
#include <cuda_fp16.h>
#include <math.h>
#include <stdint.h>

#define N_NODES  50000
#define N_EDGES  800000
#define ET       (N_EDGES + N_NODES)   // edges + self loops
#define HC       128
#define NHEAD    8
#define NEG_SLOPE 0.2f
#define LN_EPS   1e-5f
#define NB       196                   // ceil(N_NODES/256)
#define GEMM_BLOCKS 391                // ceil(N_NODES/128)
#define EB4      831                   // ceil(ET/1024): hist blocks, 4 edges/thread

// ---------------- scratch (device globals: no cudaMalloc allowed) ------------
__device__ __half g_h [(size_t)N_NODES * HC];     // x@W features, fp16 (gather payload)
__device__ float g_v  [(size_t)N_NODES * HC];     // normalized LN output (fp32)
__device__ float g_as [(size_t)N_NODES * NHEAD];
__device__ float g_ad [(size_t)N_NODES * NHEAD];
__device__ float g_w  [(size_t)ET * NHEAD];       // per-CSR-slot softmax weights
__device__ int   g_deg[N_NODES];
__device__ int   g_off[N_NODES];
__device__ int   g_bsum[256];                     // lookback scan state
__device__ int   g_rank[ET];                      // edge rank within its dst segment
__device__ int   g_src[ET];                       // CSR by destination: source ids
// weight fragment images, MMA-lane order
#define WIMG 8192
__device__ __align__(16) uint32_t g_Wb[2][WIMG];  // W^T  hi/lo
__device__ __align__(16) uint32_t g_Fb[2][WIMG];  // ffw^T hi/lo

// ---------------- bf16 split helpers ------------------------------------------
__device__ __forceinline__ uint32_t pack_hi(float a, float b) {
    return (uint32_t)__bfloat16_as_ushort(__float2bfloat16(a)) |
           ((uint32_t)__bfloat16_as_ushort(__float2bfloat16(b)) << 16);
}
__device__ __forceinline__ uint32_t pack_lo(float a, float b) {
    float ra = a - __bfloat162float(__float2bfloat16(a));
    float rb = b - __bfloat162float(__float2bfloat16(b));
    return pack_hi(ra, rb);
}

// m16n8k16 bf16 MMA, fp32 accumulate in place
__device__ __forceinline__ void mma16816(float* c, const uint32_t* a,
                                         uint32_t b0, uint32_t b1) {
    asm volatile("mma.sync.aligned.m16n8k16.row.col.f32.bf16.bf16.f32 "
                 "{%0,%1,%2,%3}, {%4,%5,%6,%7}, {%8,%9}, {%0,%1,%2,%3};"
                 : "+f"(c[0]), "+f"(c[1]), "+f"(c[2]), "+f"(c[3])
                 : "r"(a[0]), "r"(a[1]), "r"(a[2]), "r"(a[3]), "r"(b0), "r"(b1));
}

__device__ __forceinline__ void ldsm_x4(uint32_t* r, uint32_t addr) {
    asm volatile("ldmatrix.sync.aligned.m8n8.x4.shared.b16 {%0,%1,%2,%3}, [%4];"
                 : "=r"(r[0]), "=r"(r[1]), "=r"(r[2]), "=r"(r[3]) : "r"(addr));
}

__device__ __forceinline__ uint32_t smem_u32(const void* p) {
    uint32_t a;
    asm("{ .reg .u64 t; cvta.to.shared.u64 t, %1; cvt.u32.u64 %0, t; }"
        : "=r"(a) : "l"(p));
    return a;
}

// ---------------- kernel 0: init (zeros + weight fragment prep) ----------------
__global__ void init_kernel(const float* __restrict__ W,
                            const float* __restrict__ ffw) {
    const int gi = blockIdx.x * blockDim.x + threadIdx.x;
    if (gi < N_NODES) g_deg[gi] = 0;
    if (gi < 256)     g_bsum[gi] = 0;
    if (gi < WIMG) {
        const int p = gi;
        const int tile = p >> 6, r = p & 63, lane = r >> 1, reg = r & 1;
        const int nt8 = tile >> 3, ks = tile & 7;
        const int g = lane >> 2, q = lane & 3;
        const int n = nt8 * 8 + g;
        const int k0 = ks * 16 + q * 2 + reg * 8;
        {
            float w0 = W[k0 * 128 + n], w1 = W[(k0 + 1) * 128 + n];
            g_Wb[0][p] = pack_hi(w0, w1);  g_Wb[1][p] = pack_lo(w0, w1);
        }
        {
            float f0 = ffw[k0 * 128 + n], f1 = ffw[(k0 + 1) * 128 + n];
            g_Fb[0][p] = pack_hi(f0, f1);  g_Fb[1][p] = pack_lo(f0, f1);
        }
    }
}

// ---------------- shared tensor-GEMM core --------------------------------------
#define AHI_OFF 0
#define ALO_OFF 34816
#define AUX_OFF 69632
#define GT_SMEM (69632 + 1024)

__device__ __forceinline__ void gemm_core(char* smem,
                                          const float* __restrict__ in,
                                          const uint32_t* __restrict__ bhi,
                                          const uint32_t* __restrict__ blo,
                                          int tile0, float acc[4][4][4]) {
    const int t = threadIdx.x;

    uint32_t* Ah = (uint32_t*)(smem + AHI_OFF);
    uint32_t* Al = (uint32_t*)(smem + ALO_OFF);
    for (int i = t; i < 128 * 64; i += 256) {
        int row = i >> 6, c = i & 63;
        int gm = tile0 + row;
        float2 xv = make_float2(0.f, 0.f);
        if (gm < N_NODES) xv = *(const float2*)&in[(size_t)gm * 128 + c * 2];
        Ah[row * 68 + c] = pack_hi(xv.x, xv.y);
        Al[row * 68 + c] = pack_lo(xv.x, xv.y);
    }
    __syncthreads();

    const int lane = t & 31, warp = t >> 5;
    const int wm = warp & 1, wn = warp >> 1;
    const int j = lane >> 3, rr = lane & 7;

    const uint32_t sb = smem_u32(smem);
    const uint32_t a_hi0 = sb + AHI_OFF +
        (uint32_t)(wm * 64 + (j & 1) * 8 + rr) * 272u + (uint32_t)(j >> 1) * 16u;
    const uint32_t a_lo0 = a_hi0 + (ALO_OFF - AHI_OFF);

    const uint2* fh = (const uint2*)bhi;
    const uint2* fl = (const uint2*)blo;

    #pragma unroll
    for (int mt = 0; mt < 4; mt++)
        #pragma unroll
        for (int nt = 0; nt < 4; nt++)
            acc[mt][nt][0] = acc[mt][nt][1] = acc[mt][nt][2] = acc[mt][nt][3] = 0.f;

    #pragma unroll
    for (int ks = 0; ks < 8; ks++) {
        const uint32_t ko = (uint32_t)ks * 32u;
        uint32_t ah[4][4], al[4][4];
        #pragma unroll
        for (int mt = 0; mt < 4; mt++) {
            ldsm_x4(ah[mt], a_hi0 + mt * (16u * 272u) + ko);
            ldsm_x4(al[mt], a_lo0 + mt * (16u * 272u) + ko);
        }
        uint2 bh[4], bl[4];
        #pragma unroll
        for (int nt = 0; nt < 4; nt++) {
            const int fi = ((wn * 4 + nt) * 8 + ks) * 32 + lane;
            bh[nt] = __ldg(&fh[fi]);
            bl[nt] = __ldg(&fl[fi]);
        }
        #pragma unroll
        for (int mt = 0; mt < 4; mt++) {
            #pragma unroll
            for (int nt = 0; nt < 4; nt++) {
                mma16816(acc[mt][nt], ah[mt], bh[nt].x, bh[nt].y);
                mma16816(acc[mt][nt], ah[mt], bl[nt].x, bl[nt].y);
                mma16816(acc[mt][nt], al[mt], bh[nt].x, bh[nt].y);
            }
        }
    }
}

// ---------------- fused launch A: hist blocks + gemm1 blocks --------------------
__global__ void __launch_bounds__(256, 2)
fusedA_kernel(const float* __restrict__ x,
              const int* __restrict__ ei,
              const float* __restrict__ att_src,
              const float* __restrict__ att_dst) {
    if (blockIdx.x < EB4) {
        const int base = (blockIdx.x * 256 + threadIdx.x) * 4;
        int d[4];
        #pragma unroll
        for (int k = 0; k < 4; k++) {
            const int i = base + k;
            d[k] = (i < ET) ? ((i < N_EDGES) ? ei[N_EDGES + i] : (i - N_EDGES)) : -1;
        }
        #pragma unroll
        for (int k = 0; k < 4; k++)
            if (d[k] >= 0) g_rank[base + k] = atomicAdd(&g_deg[d[k]], 1);
        return;
    }

    extern __shared__ char smem[];
    const int t = threadIdx.x;
    const int tile0 = (blockIdx.x - EB4) * 128;
    if (t < 128) {
        ((float*)(smem + AUX_OFF))[t]       = att_src[t];
        ((float*)(smem + AUX_OFF + 512))[t] = att_dst[t];
    }
    float acc[4][4][4];
    gemm_core(smem, x, g_Wb[0], g_Wb[1], tile0, acc);

    const float* as_s = (const float*)(smem + AUX_OFF);
    const float* ad_s = (const float*)(smem + AUX_OFF + 512);
    const int lane = t & 31, warp = t >> 5;
    const int wm = warp & 1, wn = warp >> 1;
    const int g = lane >> 2, q = lane & 3;

    #pragma unroll
    for (int mt = 0; mt < 4; mt++) {
        const int r0 = tile0 + wm * 64 + mt * 16 + g, r1 = r0 + 8;
        float as0[2] = {0.f, 0.f}, ad0[2] = {0.f, 0.f};
        float as1[2] = {0.f, 0.f}, ad1[2] = {0.f, 0.f};
        #pragma unroll
        for (int nt = 0; nt < 4; nt++) {
            const int c = wn * 32 + nt * 8 + q * 2;
            const int hl = nt >> 1;
            as0[hl] += acc[mt][nt][0] * as_s[c] + acc[mt][nt][1] * as_s[c + 1];
            ad0[hl] += acc[mt][nt][0] * ad_s[c] + acc[mt][nt][1] * ad_s[c + 1];
            as1[hl] += acc[mt][nt][2] * as_s[c] + acc[mt][nt][3] * as_s[c + 1];
            ad1[hl] += acc[mt][nt][2] * ad_s[c] + acc[mt][nt][3] * ad_s[c + 1];
            if (r0 < N_NODES)
                *(__half2*)&g_h[(size_t)r0 * 128 + c] =
                    __floats2half2_rn(acc[mt][nt][0], acc[mt][nt][1]);
            if (r1 < N_NODES)
                *(__half2*)&g_h[(size_t)r1 * 128 + c] =
                    __floats2half2_rn(acc[mt][nt][2], acc[mt][nt][3]);
        }
        #pragma unroll
        for (int hl = 0; hl < 2; hl++) {
            #pragma unroll
            for (int o = 1; o < 4; o <<= 1) {
                as0[hl] += __shfl_xor_sync(0xFFFFFFFFu, as0[hl], o);
                ad0[hl] += __shfl_xor_sync(0xFFFFFFFFu, ad0[hl], o);
                as1[hl] += __shfl_xor_sync(0xFFFFFFFFu, as1[hl], o);
                ad1[hl] += __shfl_xor_sync(0xFFFFFFFFu, ad1[hl], o);
            }
        }
        if (q == 0) {
            const int h0 = wn * 2;
            if (r0 < N_NODES) {
                g_as[(size_t)r0 * 8 + h0]     = as0[0];
                g_as[(size_t)r0 * 8 + h0 + 1] = as0[1];
                g_ad[(size_t)r0 * 8 + h0]     = ad0[0];
                g_ad[(size_t)r0 * 8 + h0 + 1] = ad0[1];
            }
            if (r1 < N_NODES) {
                g_as[(size_t)r1 * 8 + h0]     = as1[0];
                g_as[(size_t)r1 * 8 + h0 + 1] = as1[1];
                g_ad[(size_t)r1 * 8 + h0]     = ad1[0];
                g_ad[(size_t)r1 * 8 + h0 + 1] = ad1[1];
            }
        }
    }
}

// ---------------- kernel: out = x + (v @ ffw) + ffb (tensor) --------------------
__global__ void __launch_bounds__(256, 2)
gemm2_tc_kernel(const float* __restrict__ x,
                const float* __restrict__ ffb,
                float* __restrict__ out) {
    extern __shared__ char smem[];
    const int t = threadIdx.x;
    const int tile0 = blockIdx.x * 128;
    if (t < 128) ((float*)(smem + AUX_OFF))[t] = ffb[t];

    float acc[4][4][4];
    gemm_core(smem, g_v, g_Fb[0], g_Fb[1], tile0, acc);

    const float* fb = (const float*)(smem + AUX_OFF);
    const int lane = t & 31, warp = t >> 5;
    const int wm = warp & 1, wn = warp >> 1;
    const int g = lane >> 2, q = lane & 3;

    #pragma unroll
    for (int mt = 0; mt < 4; mt++) {
        const int r0 = tile0 + wm * 64 + mt * 16 + g, r1 = r0 + 8;
        #pragma unroll
        for (int nt = 0; nt < 4; nt++) {
            const int c = wn * 32 + nt * 8 + q * 2;
            if (r0 < N_NODES) {
                float2 xr = *(const float2*)&x[(size_t)r0 * 128 + c];
                *(float2*)&out[(size_t)r0 * 128 + c] =
                    make_float2(xr.x + acc[mt][nt][0] + fb[c],
                                xr.y + acc[mt][nt][1] + fb[c + 1]);
            }
            if (r1 < N_NODES) {
                float2 xr = *(const float2*)&x[(size_t)r1 * 128 + c];
                *(float2*)&out[(size_t)r1 * 128 + c] =
                    make_float2(xr.x + acc[mt][nt][2] + fb[c],
                                xr.y + acc[mt][nt][3] + fb[c + 1]);
            }
        }
    }
}

// ---------------- kernel: single-pass decoupled-lookback exclusive scan --------
__device__ __forceinline__ int warp_incl_scan(int v, int lane) {
    #pragma unroll
    for (int o = 1; o < 32; o <<= 1) {
        int u = __shfl_up_sync(0xFFFFFFFFu, v, o);
        if (lane >= o) v += u;
    }
    return v;
}

__global__ void scan_kernel() {
    __shared__ int wsum[8];
    __shared__ int base_sh;
    const int t = threadIdx.x, lane = t & 31, w = t >> 5;
    const int b = blockIdx.x;
    const int i = b * 256 + t;
    const int v = (i < N_NODES) ? g_deg[i] : 0;
    int s = warp_incl_scan(v, lane);
    if (lane == 31) wsum[w] = s;
    __syncthreads();
    if (t < 8) {
        int ws = wsum[t];
        #pragma unroll
        for (int o = 1; o < 8; o <<= 1) {
            int u = __shfl_up_sync(0xFFu, ws, o);
            if (t >= o) ws += u;
        }
        wsum[t] = ws;
    }
    __syncthreads();
    const int incl = ((w > 0) ? wsum[w - 1] : 0) + s;
    if (t == 255) atomicExch(&g_bsum[b], incl + 1);
    if (w == 0) {
        int sum = 0;
        for (int p = b - 1 - lane; p >= 0; p -= 32) {
            int val;
            do { val = atomicAdd(&g_bsum[p], 0); } while (val == 0);
            sum += val - 1;
        }
        #pragma unroll
        for (int o = 16; o > 0; o >>= 1) sum += __shfl_xor_sync(0xFFFFFFFFu, sum, o);
        if (lane == 0) base_sh = sum;
    }
    __syncthreads();
    if (i < N_NODES) g_off[i] = base_sh + incl - v;
}

// ---------------- kernel: CSR fill + per-edge softmax weights ------------------
// Atomic-free (pos = off + rank). Also computes w = exp(leaky(a_s[s]+a_d[d]))
// for all 8 heads, stored fp32 at the CSR slot so gather reads sequentially.
__global__ void csr_fill_kernel(const int* __restrict__ ei) {
    const int base = (blockIdx.x * blockDim.x + threadIdx.x) * 4;
    int s[4], d[4], rk[4], pos[4];
    #pragma unroll
    for (int k = 0; k < 4; k++) {
        const int i = base + k;
        if (i < ET) {
            if (i < N_EDGES) { s[k] = ei[i]; d[k] = ei[N_EDGES + i]; }
            else             { s[k] = d[k] = i - N_EDGES; }
        } else s[k] = -1;
    }
    #pragma unroll
    for (int k = 0; k < 4; k++)
        if (s[k] >= 0) rk[k] = g_rank[base + k];
    #pragma unroll
    for (int k = 0; k < 4; k++)
        if (s[k] >= 0) pos[k] = g_off[d[k]] + rk[k];
    #pragma unroll
    for (int k = 0; k < 4; k++) {
        if (s[k] < 0) continue;
        g_src[pos[k]] = s[k];
        float4 a0 = *(const float4*)&g_as[(size_t)s[k] * 8];
        float4 a1 = *(const float4*)&g_as[(size_t)s[k] * 8 + 4];
        float4 b0 = *(const float4*)&g_ad[(size_t)d[k] * 8];
        float4 b1 = *(const float4*)&g_ad[(size_t)d[k] * 8 + 4];
        float l[8] = { a0.x + b0.x, a0.y + b0.y, a0.z + b0.z, a0.w + b0.w,
                       a1.x + b1.x, a1.y + b1.y, a1.z + b1.z, a1.w + b1.w };
        #pragma unroll
        for (int h = 0; h < 8; h++) {
            float v = fmaxf(l[h], NEG_SLOPE * l[h]);
            l[h] = __expf(v);
        }
        float* dst = &g_w[(size_t)pos[k] * 8];
        *(float4*)&dst[0] = make_float4(l[0], l[1], l[2], l[3]);
        *(float4*)&dst[4] = make_float4(l[4], l[5], l[6], l[7]);
    }
}

// ---------------- kernel: gather + softmax + bias + LayerNorm -> g_v -----------
// Half-warp per edge; per-edge weight read from g_w (sequential, precomputed).
__global__ void gather_ln_kernel(const float* __restrict__ conv_bias,
                                 const float* __restrict__ ln_g,
                                 const float* __restrict__ ln_b) {
    const int wid  = (blockIdx.x * blockDim.x + threadIdx.x) >> 5;
    const int lane = threadIdx.x & 31;
    if (wid >= N_NODES) return;
    const int n    = wid;
    const int half = lane >> 4;       // 0 or 1
    const int hl   = lane & 15;       // 0..15
    const int hd   = hl >> 1;         // head
    const int cb8  = hl * 8;          // channel base (8 channels per lane)
    const int start = g_off[n];
    const int end   = start + g_deg[n];

    const char* hbase = (const char*)g_h;
    const unsigned coff = (unsigned)cb8 * 2u;

    float wsum = 0.f;
    float acc[8];
    #pragma unroll
    for (int i = 0; i < 8; i++) acc[i] = 0.f;

    int e = start + half;
    for (; e + 2 < end; e += 4) {
        const int s0 = g_src[e], s1 = g_src[e + 2];
        const float w0 = g_w[(size_t)e * 8 + hd];
        const float w1 = g_w[(size_t)(e + 2) * 8 + hd];
        const uint4 u0 = *(const uint4*)(hbase + ((unsigned)s0 << 8) + coff);
        const uint4 u1 = *(const uint4*)(hbase + ((unsigned)s1 << 8) + coff);
        wsum += w0 + w1;
        {
            float2 f0 = __half22float2(*(const __half2*)&u0.x);
            float2 f1 = __half22float2(*(const __half2*)&u0.y);
            float2 f2 = __half22float2(*(const __half2*)&u0.z);
            float2 f3 = __half22float2(*(const __half2*)&u0.w);
            acc[0] += w0 * f0.x; acc[1] += w0 * f0.y;
            acc[2] += w0 * f1.x; acc[3] += w0 * f1.y;
            acc[4] += w0 * f2.x; acc[5] += w0 * f2.y;
            acc[6] += w0 * f3.x; acc[7] += w0 * f3.y;
        }
        {
            float2 f0 = __half22float2(*(const __half2*)&u1.x);
            float2 f1 = __half22float2(*(const __half2*)&u1.y);
            float2 f2 = __half22float2(*(const __half2*)&u1.z);
            float2 f3 = __half22float2(*(const __half2*)&u1.w);
            acc[0] += w1 * f0.x; acc[1] += w1 * f0.y;
            acc[2] += w1 * f1.x; acc[3] += w1 * f1.y;
            acc[4] += w1 * f2.x; acc[5] += w1 * f2.y;
            acc[6] += w1 * f3.x; acc[7] += w1 * f3.y;
        }
    }
    for (; e < end; e += 2) {
        const int s0 = g_src[e];
        const float w0 = g_w[(size_t)e * 8 + hd];
        const uint4 u0 = *(const uint4*)(hbase + ((unsigned)s0 << 8) + coff);
        wsum += w0;
        float2 f0 = __half22float2(*(const __half2*)&u0.x);
        float2 f1 = __half22float2(*(const __half2*)&u0.y);
        float2 f2 = __half22float2(*(const __half2*)&u0.z);
        float2 f3 = __half22float2(*(const __half2*)&u0.w);
        acc[0] += w0 * f0.x; acc[1] += w0 * f0.y;
        acc[2] += w0 * f1.x; acc[3] += w0 * f1.y;
        acc[4] += w0 * f2.x; acc[5] += w0 * f2.y;
        acc[6] += w0 * f3.x; acc[7] += w0 * f3.y;
    }

    wsum += __shfl_xor_sync(0xFFFFFFFFu, wsum, 16);
    #pragma unroll
    for (int i = 0; i < 8; i++) acc[i] += __shfl_xor_sync(0xFFFFFFFFu, acc[i], 16);

    const float dinv = 1.0f / wsum;
    const float4 cb0 = *(const float4*)&conv_bias[cb8];
    const float4 cb1 = *(const float4*)&conv_bias[cb8 + 4];
    float v[8];
    v[0] = acc[0] * dinv + cb0.x; v[1] = acc[1] * dinv + cb0.y;
    v[2] = acc[2] * dinv + cb0.z; v[3] = acc[3] * dinv + cb0.w;
    v[4] = acc[4] * dinv + cb1.x; v[5] = acc[5] * dinv + cb1.y;
    v[6] = acc[6] * dinv + cb1.z; v[7] = acc[7] * dinv + cb1.w;

    float s = ((v[0] + v[1]) + (v[2] + v[3])) + ((v[4] + v[5]) + (v[6] + v[7]));
    #pragma unroll
    for (int o = 16; o > 0; o >>= 1) s += __shfl_xor_sync(0xFFFFFFFFu, s, o);
    const float mu = s * (1.0f / 256.0f);

    float sq = 0.f;
    #pragma unroll
    for (int i = 0; i < 8; i++) { v[i] -= mu; sq += v[i] * v[i]; }
    #pragma unroll
    for (int o = 16; o > 0; o >>= 1) sq += __shfl_xor_sync(0xFFFFFFFFu, sq, o);
    const float rstd = rsqrtf(sq * (1.0f / 256.0f) + LN_EPS);

    if (half == 0) {
        const float4 gg0 = *(const float4*)&ln_g[cb8];
        const float4 gg1 = *(const float4*)&ln_g[cb8 + 4];
        const float4 bb0 = *(const float4*)&ln_b[cb8];
        const float4 bb1 = *(const float4*)&ln_b[cb8 + 4];
        float* dst = &g_v[(size_t)n * HC + cb8];
        *(float4*)&dst[0] = make_float4(v[0]*rstd*gg0.x + bb0.x, v[1]*rstd*gg0.y + bb0.y,
                                        v[2]*rstd*gg0.z + bb0.z, v[3]*rstd*gg0.w + bb0.w);
        *(float4*)&dst[4] = make_float4(v[4]*rstd*gg1.x + bb1.x, v[5]*rstd*gg1.y + bb1.y,
                                        v[6]*rstd*gg1.z + bb1.z, v[7]*rstd*gg1.w + bb1.w);
    }
}

// ---------------- launch -------------------------------------------------------
extern "C" void kernel_launch(void* const* d_in, const int* in_sizes, int n_in,
                              void* d_out, int out_size) {
    const float* x        = (const float*)d_in[0];
    const int*   ei       = (const int*)  d_in[1];
    const float* W        = (const float*)d_in[2];
    const float* att_src  = (const float*)d_in[3];
    const float* att_dst  = (const float*)d_in[4];
    const float* conv_b   = (const float*)d_in[5];
    const float* ln_g     = (const float*)d_in[6];
    const float* ln_b     = (const float*)d_in[7];
    const float* ffw      = (const float*)d_in[8];
    const float* ffb      = (const float*)d_in[9];
    float*       out      = (float*)d_out;

    cudaFuncSetAttribute(fusedA_kernel,   cudaFuncAttributeMaxDynamicSharedMemorySize, GT_SMEM);
    cudaFuncSetAttribute(gemm2_tc_kernel, cudaFuncAttributeMaxDynamicSharedMemorySize, GT_SMEM);

    const int WB = (N_NODES * 32 + 255) / 256;

    init_kernel      <<<NB, 256>>>(W, ffw);                                          // 1
    fusedA_kernel    <<<EB4 + GEMM_BLOCKS, 256, GT_SMEM>>>(x, ei, att_src, att_dst); // 2
    scan_kernel      <<<NB, 256>>>();                                                // 3
    csr_fill_kernel  <<<EB4, 256>>>(ei);                                             // 4
    gather_ln_kernel <<<WB, 256>>>(conv_b, ln_g, ln_b);                              // 5
    gemm2_tc_kernel  <<<GEMM_BLOCKS, 256, GT_SMEM>>>(x, ffb, out);                   // 6 (profiled)
}

// round 16
// speedup vs baseline: 1.1947x; 1.1947x over previous
#include <cuda_runtime.h>
#include <cuda_bf16.h>
#include <cuda_fp16.h>
#include <math.h>
#include <stdint.h>

#define N_NODES  50000
#define N_EDGES  800000
#define ET       (N_EDGES + N_NODES)   // edges + self loops
#define HC       128
#define NHEAD    8
#define NEG_SLOPE 0.2f
#define LN_EPS   1e-5f
#define NB       196                   // ceil(N_NODES/256)
#define GEMM_BLOCKS 391                // ceil(N_NODES/128)
#define EB4      831                   // ceil(ET/1024): hist blocks, 4 edges/thread

// ---------------- scratch (device globals: no cudaMalloc allowed) ------------
__device__ __half g_h [(size_t)N_NODES * HC];     // x@W features, fp16 (gather payload)
__device__ float g_v  [(size_t)N_NODES * HC];     // normalized LN output (fp32)
__device__ float g_as [(size_t)N_NODES * NHEAD];
__device__ float g_ad [(size_t)N_NODES * NHEAD];
__device__ int   g_deg[N_NODES];
__device__ int   g_off[N_NODES];
__device__ int   g_bsum[256];                     // lookback scan state
__device__ int   g_rank[ET];                      // edge rank within its dst segment
__device__ int   g_src[ET];                       // CSR by destination: source ids
// weight fragment images, MMA-lane order
#define WIMG 8192
__device__ __align__(16) uint32_t g_Wb[2][WIMG];  // W^T  hi/lo
__device__ __align__(16) uint32_t g_Fb[2][WIMG];  // ffw^T hi/lo

// ---------------- bf16 split helpers ------------------------------------------
__device__ __forceinline__ uint32_t pack_hi(float a, float b) {
    return (uint32_t)__bfloat16_as_ushort(__float2bfloat16(a)) |
           ((uint32_t)__bfloat16_as_ushort(__float2bfloat16(b)) << 16);
}
__device__ __forceinline__ uint32_t pack_lo(float a, float b) {
    float ra = a - __bfloat162float(__float2bfloat16(a));
    float rb = b - __bfloat162float(__float2bfloat16(b));
    return pack_hi(ra, rb);
}

// m16n8k16 bf16 MMA, fp32 accumulate in place
__device__ __forceinline__ void mma16816(float* c, const uint32_t* a,
                                         uint32_t b0, uint32_t b1) {
    asm volatile("mma.sync.aligned.m16n8k16.row.col.f32.bf16.bf16.f32 "
                 "{%0,%1,%2,%3}, {%4,%5,%6,%7}, {%8,%9}, {%0,%1,%2,%3};"
                 : "+f"(c[0]), "+f"(c[1]), "+f"(c[2]), "+f"(c[3])
                 : "r"(a[0]), "r"(a[1]), "r"(a[2]), "r"(a[3]), "r"(b0), "r"(b1));
}

__device__ __forceinline__ void ldsm_x4(uint32_t* r, uint32_t addr) {
    asm volatile("ldmatrix.sync.aligned.m8n8.x4.shared.b16 {%0,%1,%2,%3}, [%4];"
                 : "=r"(r[0]), "=r"(r[1]), "=r"(r[2]), "=r"(r[3]) : "r"(addr));
}

__device__ __forceinline__ uint32_t smem_u32(const void* p) {
    uint32_t a;
    asm("{ .reg .u64 t; cvta.to.shared.u64 t, %1; cvt.u32.u64 %0, t; }"
        : "=r"(a) : "l"(p));
    return a;
}

// ---------------- kernel 0: init (zeros + weight fragment prep) ----------------
__global__ void init_kernel(const float* __restrict__ W,
                            const float* __restrict__ ffw) {
    const int gi = blockIdx.x * blockDim.x + threadIdx.x;
    if (gi < N_NODES) g_deg[gi] = 0;
    if (gi < 256)     g_bsum[gi] = 0;
    if (gi < WIMG) {
        const int p = gi;
        const int tile = p >> 6, r = p & 63, lane = r >> 1, reg = r & 1;
        const int nt8 = tile >> 3, ks = tile & 7;
        const int g = lane >> 2, q = lane & 3;
        const int n = nt8 * 8 + g;
        const int k0 = ks * 16 + q * 2 + reg * 8;
        {
            float w0 = W[k0 * 128 + n], w1 = W[(k0 + 1) * 128 + n];
            g_Wb[0][p] = pack_hi(w0, w1);  g_Wb[1][p] = pack_lo(w0, w1);
        }
        {
            float f0 = ffw[k0 * 128 + n], f1 = ffw[(k0 + 1) * 128 + n];
            g_Fb[0][p] = pack_hi(f0, f1);  g_Fb[1][p] = pack_lo(f0, f1);
        }
    }
}

// ---------------- shared tensor-GEMM core --------------------------------------
#define AHI_OFF 0
#define ALO_OFF 34816
#define AUX_OFF 69632
#define GT_SMEM (69632 + 1024)

__device__ __forceinline__ void gemm_core(char* smem,
                                          const float* __restrict__ in,
                                          const uint32_t* __restrict__ bhi,
                                          const uint32_t* __restrict__ blo,
                                          int tile0, float acc[4][4][4]) {
    const int t = threadIdx.x;

    uint32_t* Ah = (uint32_t*)(smem + AHI_OFF);
    uint32_t* Al = (uint32_t*)(smem + ALO_OFF);
    for (int i = t; i < 128 * 64; i += 256) {
        int row = i >> 6, c = i & 63;
        int gm = tile0 + row;
        float2 xv = make_float2(0.f, 0.f);
        if (gm < N_NODES) xv = *(const float2*)&in[(size_t)gm * 128 + c * 2];
        Ah[row * 68 + c] = pack_hi(xv.x, xv.y);
        Al[row * 68 + c] = pack_lo(xv.x, xv.y);
    }
    __syncthreads();

    const int lane = t & 31, warp = t >> 5;
    const int wm = warp & 1, wn = warp >> 1;
    const int j = lane >> 3, rr = lane & 7;

    const uint32_t sb = smem_u32(smem);
    const uint32_t a_hi0 = sb + AHI_OFF +
        (uint32_t)(wm * 64 + (j & 1) * 8 + rr) * 272u + (uint32_t)(j >> 1) * 16u;
    const uint32_t a_lo0 = a_hi0 + (ALO_OFF - AHI_OFF);

    const uint2* fh = (const uint2*)bhi;
    const uint2* fl = (const uint2*)blo;

    #pragma unroll
    for (int mt = 0; mt < 4; mt++)
        #pragma unroll
        for (int nt = 0; nt < 4; nt++)
            acc[mt][nt][0] = acc[mt][nt][1] = acc[mt][nt][2] = acc[mt][nt][3] = 0.f;

    #pragma unroll
    for (int ks = 0; ks < 8; ks++) {
        const uint32_t ko = (uint32_t)ks * 32u;
        uint32_t ah[4][4], al[4][4];
        #pragma unroll
        for (int mt = 0; mt < 4; mt++) {
            ldsm_x4(ah[mt], a_hi0 + mt * (16u * 272u) + ko);
            ldsm_x4(al[mt], a_lo0 + mt * (16u * 272u) + ko);
        }
        uint2 bh[4], bl[4];
        #pragma unroll
        for (int nt = 0; nt < 4; nt++) {
            const int fi = ((wn * 4 + nt) * 8 + ks) * 32 + lane;
            bh[nt] = __ldg(&fh[fi]);
            bl[nt] = __ldg(&fl[fi]);
        }
        #pragma unroll
        for (int mt = 0; mt < 4; mt++) {
            #pragma unroll
            for (int nt = 0; nt < 4; nt++) {
                mma16816(acc[mt][nt], ah[mt], bh[nt].x, bh[nt].y);
                mma16816(acc[mt][nt], ah[mt], bl[nt].x, bl[nt].y);
                mma16816(acc[mt][nt], al[mt], bh[nt].x, bh[nt].y);
            }
        }
    }
}

// ---------------- fused launch A: gemm1 blocks FIRST, hist blocks after --------
// GEMM tiles fill all SM slots immediately (critical path); short hist blocks
// backfill as tiles retire, hiding inside the GEMM shadow.
__global__ void __launch_bounds__(256, 2)
fusedA_kernel(const float* __restrict__ x,
              const int* __restrict__ ei,
              const float* __restrict__ att_src,
              const float* __restrict__ att_dst) {
    if (blockIdx.x >= GEMM_BLOCKS) {
        // ---- hist path ----
        const int base = ((blockIdx.x - GEMM_BLOCKS) * 256 + threadIdx.x) * 4;
        int d[4];
        #pragma unroll
        for (int k = 0; k < 4; k++) {
            const int i = base + k;
            d[k] = (i < ET) ? ((i < N_EDGES) ? ei[N_EDGES + i] : (i - N_EDGES)) : -1;
        }
        #pragma unroll
        for (int k = 0; k < 4; k++)
            if (d[k] >= 0) g_rank[base + k] = atomicAdd(&g_deg[d[k]], 1);
        return;
    }

    // ---- gemm1 path ----
    extern __shared__ char smem[];
    const int t = threadIdx.x;
    const int tile0 = blockIdx.x * 128;
    if (t < 128) {
        ((float*)(smem + AUX_OFF))[t]       = att_src[t];
        ((float*)(smem + AUX_OFF + 512))[t] = att_dst[t];
    }
    float acc[4][4][4];
    gemm_core(smem, x, g_Wb[0], g_Wb[1], tile0, acc);

    const float* as_s = (const float*)(smem + AUX_OFF);
    const float* ad_s = (const float*)(smem + AUX_OFF + 512);
    const int lane = t & 31, warp = t >> 5;
    const int wm = warp & 1, wn = warp >> 1;
    const int g = lane >> 2, q = lane & 3;

    #pragma unroll
    for (int mt = 0; mt < 4; mt++) {
        const int r0 = tile0 + wm * 64 + mt * 16 + g, r1 = r0 + 8;
        float as0[2] = {0.f, 0.f}, ad0[2] = {0.f, 0.f};
        float as1[2] = {0.f, 0.f}, ad1[2] = {0.f, 0.f};
        #pragma unroll
        for (int nt = 0; nt < 4; nt++) {
            const int c = wn * 32 + nt * 8 + q * 2;
            const int hl = nt >> 1;
            as0[hl] += acc[mt][nt][0] * as_s[c] + acc[mt][nt][1] * as_s[c + 1];
            ad0[hl] += acc[mt][nt][0] * ad_s[c] + acc[mt][nt][1] * ad_s[c + 1];
            as1[hl] += acc[mt][nt][2] * as_s[c] + acc[mt][nt][3] * as_s[c + 1];
            ad1[hl] += acc[mt][nt][2] * ad_s[c] + acc[mt][nt][3] * ad_s[c + 1];
            if (r0 < N_NODES)
                *(__half2*)&g_h[(size_t)r0 * 128 + c] =
                    __floats2half2_rn(acc[mt][nt][0], acc[mt][nt][1]);
            if (r1 < N_NODES)
                *(__half2*)&g_h[(size_t)r1 * 128 + c] =
                    __floats2half2_rn(acc[mt][nt][2], acc[mt][nt][3]);
        }
        #pragma unroll
        for (int hl = 0; hl < 2; hl++) {
            #pragma unroll
            for (int o = 1; o < 4; o <<= 1) {
                as0[hl] += __shfl_xor_sync(0xFFFFFFFFu, as0[hl], o);
                ad0[hl] += __shfl_xor_sync(0xFFFFFFFFu, ad0[hl], o);
                as1[hl] += __shfl_xor_sync(0xFFFFFFFFu, as1[hl], o);
                ad1[hl] += __shfl_xor_sync(0xFFFFFFFFu, ad1[hl], o);
            }
        }
        if (q == 0) {
            const int h0 = wn * 2;
            if (r0 < N_NODES) {
                g_as[(size_t)r0 * 8 + h0]     = as0[0];
                g_as[(size_t)r0 * 8 + h0 + 1] = as0[1];
                g_ad[(size_t)r0 * 8 + h0]     = ad0[0];
                g_ad[(size_t)r0 * 8 + h0 + 1] = ad0[1];
            }
            if (r1 < N_NODES) {
                g_as[(size_t)r1 * 8 + h0]     = as1[0];
                g_as[(size_t)r1 * 8 + h0 + 1] = as1[1];
                g_ad[(size_t)r1 * 8 + h0]     = ad1[0];
                g_ad[(size_t)r1 * 8 + h0 + 1] = ad1[1];
            }
        }
    }
}

// ---------------- kernel: out = x + (v @ ffw) + ffb (tensor) --------------------
__global__ void __launch_bounds__(256, 2)
gemm2_tc_kernel(const float* __restrict__ x,
                const float* __restrict__ ffb,
                float* __restrict__ out) {
    extern __shared__ char smem[];
    const int t = threadIdx.x;
    const int tile0 = blockIdx.x * 128;
    if (t < 128) ((float*)(smem + AUX_OFF))[t] = ffb[t];

    float acc[4][4][4];
    gemm_core(smem, g_v, g_Fb[0], g_Fb[1], tile0, acc);

    const float* fb = (const float*)(smem + AUX_OFF);
    const int lane = t & 31, warp = t >> 5;
    const int wm = warp & 1, wn = warp >> 1;
    const int g = lane >> 2, q = lane & 3;

    #pragma unroll
    for (int mt = 0; mt < 4; mt++) {
        const int r0 = tile0 + wm * 64 + mt * 16 + g, r1 = r0 + 8;
        #pragma unroll
        for (int nt = 0; nt < 4; nt++) {
            const int c = wn * 32 + nt * 8 + q * 2;
            if (r0 < N_NODES) {
                float2 xr = *(const float2*)&x[(size_t)r0 * 128 + c];
                *(float2*)&out[(size_t)r0 * 128 + c] =
                    make_float2(xr.x + acc[mt][nt][0] + fb[c],
                                xr.y + acc[mt][nt][1] + fb[c + 1]);
            }
            if (r1 < N_NODES) {
                float2 xr = *(const float2*)&x[(size_t)r1 * 128 + c];
                *(float2*)&out[(size_t)r1 * 128 + c] =
                    make_float2(xr.x + acc[mt][nt][2] + fb[c],
                                xr.y + acc[mt][nt][3] + fb[c + 1]);
            }
        }
    }
}

// ---------------- kernel: single-pass decoupled-lookback exclusive scan --------
__device__ __forceinline__ int warp_incl_scan(int v, int lane) {
    #pragma unroll
    for (int o = 1; o < 32; o <<= 1) {
        int u = __shfl_up_sync(0xFFFFFFFFu, v, o);
        if (lane >= o) v += u;
    }
    return v;
}

__global__ void scan_kernel() {
    __shared__ int wsum[8];
    __shared__ int base_sh;
    const int t = threadIdx.x, lane = t & 31, w = t >> 5;
    const int b = blockIdx.x;
    const int i = b * 256 + t;
    const int v = (i < N_NODES) ? g_deg[i] : 0;
    int s = warp_incl_scan(v, lane);
    if (lane == 31) wsum[w] = s;
    __syncthreads();
    if (t < 8) {
        int ws = wsum[t];
        #pragma unroll
        for (int o = 1; o < 8; o <<= 1) {
            int u = __shfl_up_sync(0xFFu, ws, o);
            if (t >= o) ws += u;
        }
        wsum[t] = ws;
    }
    __syncthreads();
    const int incl = ((w > 0) ? wsum[w - 1] : 0) + s;
    if (t == 255) atomicExch(&g_bsum[b], incl + 1);
    if (w == 0) {
        int sum = 0;
        for (int p = b - 1 - lane; p >= 0; p -= 32) {
            int val;
            do { val = atomicAdd(&g_bsum[p], 0); } while (val == 0);
            sum += val - 1;
        }
        #pragma unroll
        for (int o = 16; o > 0; o >>= 1) sum += __shfl_xor_sync(0xFFFFFFFFu, sum, o);
        if (lane == 0) base_sh = sum;
    }
    __syncthreads();
    if (i < N_NODES) g_off[i] = base_sh + incl - v;
}

// ---------------- kernel: CSR fill, atomic-free (4 edges/thread) ---------------
__global__ void csr_fill_kernel(const int* __restrict__ ei) {
    const int base = (blockIdx.x * blockDim.x + threadIdx.x) * 4;
    #pragma unroll
    for (int k = 0; k < 4; k++) {
        const int i = base + k;
        if (i >= ET) return;
        int s, d;
        if (i < N_EDGES) { s = ei[i]; d = ei[N_EDGES + i]; }
        else             { s = d = i - N_EDGES; }
        g_src[g_off[d] + g_rank[i]] = s;
    }
}

// ---------------- kernel: gather + softmax + bias + LayerNorm -> g_v -----------
// Half-warp per edge: lanes 0-15 take even CSR slots, 16-31 odd. Each lane owns
// 8 channels (one LDG.128 of fp16). Per-edge scalar work issues once per TWO
// edges. Halves combined by shfl; warp reductions use /256 (channels doubled).
__global__ void gather_ln_kernel(const float* __restrict__ conv_bias,
                                 const float* __restrict__ ln_g,
                                 const float* __restrict__ ln_b) {
    const int wid  = (blockIdx.x * blockDim.x + threadIdx.x) >> 5;
    const int lane = threadIdx.x & 31;
    if (wid >= N_NODES) return;
    const int n    = wid;
    const int half = lane >> 4;       // 0 or 1
    const int hl   = lane & 15;       // 0..15
    const int hd   = hl >> 1;         // head
    const int cb8  = hl * 8;          // channel base (8 channels per lane)
    const int start = g_off[n];
    const int end   = start + g_deg[n];
    const float ad  = g_ad[(unsigned)n * 8u + hd];

    const char* hbase = (const char*)g_h;
    const unsigned coff = (unsigned)cb8 * 2u;

    float wsum = 0.f;
    float acc[8];
    #pragma unroll
    for (int i = 0; i < 8; i++) acc[i] = 0.f;

    int e = start + half;
    for (; e + 2 < end; e += 4) {
        const int s0 = g_src[e], s1 = g_src[e + 2];
        float l0 = g_as[(unsigned)s0 * 8u + hd] + ad;
        float l1 = g_as[(unsigned)s1 * 8u + hd] + ad;
        const uint4 u0 = *(const uint4*)(hbase + ((unsigned)s0 << 8) + coff);
        const uint4 u1 = *(const uint4*)(hbase + ((unsigned)s1 << 8) + coff);
        l0 = fmaxf(l0, NEG_SLOPE * l0);
        l1 = fmaxf(l1, NEG_SLOPE * l1);
        const float w0 = __expf(l0), w1 = __expf(l1);
        wsum += w0 + w1;
        {
            float2 f0 = __half22float2(*(const __half2*)&u0.x);
            float2 f1 = __half22float2(*(const __half2*)&u0.y);
            float2 f2 = __half22float2(*(const __half2*)&u0.z);
            float2 f3 = __half22float2(*(const __half2*)&u0.w);
            acc[0] += w0 * f0.x; acc[1] += w0 * f0.y;
            acc[2] += w0 * f1.x; acc[3] += w0 * f1.y;
            acc[4] += w0 * f2.x; acc[5] += w0 * f2.y;
            acc[6] += w0 * f3.x; acc[7] += w0 * f3.y;
        }
        {
            float2 f0 = __half22float2(*(const __half2*)&u1.x);
            float2 f1 = __half22float2(*(const __half2*)&u1.y);
            float2 f2 = __half22float2(*(const __half2*)&u1.z);
            float2 f3 = __half22float2(*(const __half2*)&u1.w);
            acc[0] += w1 * f0.x; acc[1] += w1 * f0.y;
            acc[2] += w1 * f1.x; acc[3] += w1 * f1.y;
            acc[4] += w1 * f2.x; acc[5] += w1 * f2.y;
            acc[6] += w1 * f3.x; acc[7] += w1 * f3.y;
        }
    }
    for (; e < end; e += 2) {
        const int s0 = g_src[e];
        float l0 = g_as[(unsigned)s0 * 8u + hd] + ad;
        const uint4 u0 = *(const uint4*)(hbase + ((unsigned)s0 << 8) + coff);
        l0 = fmaxf(l0, NEG_SLOPE * l0);
        const float w0 = __expf(l0);
        wsum += w0;
        float2 f0 = __half22float2(*(const __half2*)&u0.x);
        float2 f1 = __half22float2(*(const __half2*)&u0.y);
        float2 f2 = __half22float2(*(const __half2*)&u0.z);
        float2 f3 = __half22float2(*(const __half2*)&u0.w);
        acc[0] += w0 * f0.x; acc[1] += w0 * f0.y;
        acc[2] += w0 * f1.x; acc[3] += w0 * f1.y;
        acc[4] += w0 * f2.x; acc[5] += w0 * f2.y;
        acc[6] += w0 * f3.x; acc[7] += w0 * f3.y;
    }

    wsum += __shfl_xor_sync(0xFFFFFFFFu, wsum, 16);
    #pragma unroll
    for (int i = 0; i < 8; i++) acc[i] += __shfl_xor_sync(0xFFFFFFFFu, acc[i], 16);

    const float dinv = 1.0f / wsum;
    const float4 cb0 = *(const float4*)&conv_bias[cb8];
    const float4 cb1 = *(const float4*)&conv_bias[cb8 + 4];
    float v[8];
    v[0] = acc[0] * dinv + cb0.x; v[1] = acc[1] * dinv + cb0.y;
    v[2] = acc[2] * dinv + cb0.z; v[3] = acc[3] * dinv + cb0.w;
    v[4] = acc[4] * dinv + cb1.x; v[5] = acc[5] * dinv + cb1.y;
    v[6] = acc[6] * dinv + cb1.z; v[7] = acc[7] * dinv + cb1.w;

    float s = ((v[0] + v[1]) + (v[2] + v[3])) + ((v[4] + v[5]) + (v[6] + v[7]));
    #pragma unroll
    for (int o = 16; o > 0; o >>= 1) s += __shfl_xor_sync(0xFFFFFFFFu, s, o);
    const float mu = s * (1.0f / 256.0f);

    float sq = 0.f;
    #pragma unroll
    for (int i = 0; i < 8; i++) { v[i] -= mu; sq += v[i] * v[i]; }
    #pragma unroll
    for (int o = 16; o > 0; o >>= 1) sq += __shfl_xor_sync(0xFFFFFFFFu, sq, o);
    const float rstd = rsqrtf(sq * (1.0f / 256.0f) + LN_EPS);

    if (half == 0) {
        const float4 gg0 = *(const float4*)&ln_g[cb8];
        const float4 gg1 = *(const float4*)&ln_g[cb8 + 4];
        const float4 bb0 = *(const float4*)&ln_b[cb8];
        const float4 bb1 = *(const float4*)&ln_b[cb8 + 4];
        float* dst = &g_v[(size_t)n * HC + cb8];
        *(float4*)&dst[0] = make_float4(v[0]*rstd*gg0.x + bb0.x, v[1]*rstd*gg0.y + bb0.y,
                                        v[2]*rstd*gg0.z + bb0.z, v[3]*rstd*gg0.w + bb0.w);
        *(float4*)&dst[4] = make_float4(v[4]*rstd*gg1.x + bb1.x, v[5]*rstd*gg1.y + bb1.y,
                                        v[6]*rstd*gg1.z + bb1.z, v[7]*rstd*gg1.w + bb1.w);
    }
}

// ---------------- launch -------------------------------------------------------
extern "C" void kernel_launch(void* const* d_in, const int* in_sizes, int n_in,
                              void* d_out, int out_size) {
    const float* x        = (const float*)d_in[0];
    const int*   ei       = (const int*)  d_in[1];
    const float* W        = (const float*)d_in[2];
    const float* att_src  = (const float*)d_in[3];
    const float* att_dst  = (const float*)d_in[4];
    const float* conv_b   = (const float*)d_in[5];
    const float* ln_g     = (const float*)d_in[6];
    const float* ln_b     = (const float*)d_in[7];
    const float* ffw      = (const float*)d_in[8];
    const float* ffb      = (const float*)d_in[9];
    float*       out      = (float*)d_out;

    cudaFuncSetAttribute(fusedA_kernel,   cudaFuncAttributeMaxDynamicSharedMemorySize, GT_SMEM);
    cudaFuncSetAttribute(gemm2_tc_kernel, cudaFuncAttributeMaxDynamicSharedMemorySize, GT_SMEM);

    const int WB = (N_NODES * 32 + 255) / 256;

    init_kernel      <<<NB, 256>>>(W, ffw);                                          // 1
    fusedA_kernel    <<<GEMM_BLOCKS + EB4, 256, GT_SMEM>>>(x, ei, att_src, att_dst); // 2
    scan_kernel      <<<NB, 256>>>();                                                // 3
    csr_fill_kernel  <<<EB4, 256>>>(ei);                                             // 4
    gather_ln_kernel <<<WB, 256>>>(conv_b, ln_g, ln_b);                              // 5
    gemm2_tc_kernel  <<<GEMM_BLOCKS, 256, GT_SMEM>>>(x, ffb, out);                   // 6 (profiled)
}